// round 5
// baseline (speedup 1.0000x reference)
#include <cuda_runtime.h>
#include <cuda_bf16.h>

#define FEATS 64
#define N_SRC_MAX 100000
#define N_EDGES_MAX 1100000
#define TILE_ROWS 128
#define SCAN_B 128
#define SCAN_T 256

// ---------------------------------------------------------------------------
// Device scratch (no allocation allowed in kernel_launch)
// ---------------------------------------------------------------------------
__device__ int g_count[N_SRC_MAX];    // per-dst degree (exact, int)
__device__ int g_off[N_SRC_MAX];      // exclusive prefix of counts
__device__ int g_cursor[N_SRC_MAX];   // mutable copy of g_off for CSR fill
__device__ int g_csr[N_EDGES_MAX];    // src ids grouped by dst
__device__ int g_part[SCAN_B];        // scan block partials

// ---------------------------------------------------------------------------
// 1) zero the histogram
// ---------------------------------------------------------------------------
__global__ void zero_counts_kernel(int n) {
    int stride = gridDim.x * blockDim.x;
    for (int i = blockIdx.x * blockDim.x + threadIdx.x; i < n; i += stride)
        g_count[i] = 0;
}

// ---------------------------------------------------------------------------
// 2) histogram of dst: integer atomics only (REDG spread ~1.29cyc/lane)
// ---------------------------------------------------------------------------
__global__ void hist_kernel(const int* __restrict__ dst, int n_edges) {
    int stride = gridDim.x * blockDim.x;
    for (int e = blockIdx.x * blockDim.x + threadIdx.x; e < n_edges; e += stride)
        atomicAdd(&g_count[__ldg(dst + e)], 1);
}

// ---------------------------------------------------------------------------
// 3) exclusive scan of counts: reduce -> scan partials -> final
// ---------------------------------------------------------------------------
__global__ void scan_reduce_kernel(int n, int C) {
    __shared__ int sh[SCAN_T];
    int b = blockIdx.x, t = threadIdx.x;
    int start = b * C;
    int end = min(start + C, n);
    int s = 0;
    for (int i = start + t; i < end; i += SCAN_T) s += g_count[i];
    sh[t] = s; __syncthreads();
    for (int o = SCAN_T / 2; o > 0; o >>= 1) {
        if (t < o) sh[t] += sh[t + o];
        __syncthreads();
    }
    if (t == 0) g_part[b] = sh[0];
}

__global__ void scan_partials_kernel() {
    if (threadIdx.x == 0 && blockIdx.x == 0) {
        int run = 0;
        for (int i = 0; i < SCAN_B; i++) {
            int v = g_part[i];
            g_part[i] = run;
            run += v;
        }
    }
}

__global__ void scan_final_kernel(int n, int C, int S) {
    __shared__ int sh[SCAN_T];
    int b = blockIdx.x, t = threadIdx.x;
    int blockbase = g_part[b];
    int cend = min(b * C + C, n);
    int tstart = b * C + t * S;
    int tend = min(tstart + S, cend);
    int s = 0;
    for (int i = tstart; i < tend; i++) s += g_count[i];
    // inclusive Hillis-Steele scan of thread partials
    sh[t] = s; __syncthreads();
    for (int o = 1; o < SCAN_T; o <<= 1) {
        int v = (t >= o) ? sh[t - o] : 0;
        __syncthreads();
        sh[t] += v;
        __syncthreads();
    }
    int run = blockbase + sh[t] - s;   // exclusive
    for (int i = tstart; i < tend; i++) {
        g_off[i] = run;
        g_cursor[i] = run;
        run += g_count[i];
    }
}

// ---------------------------------------------------------------------------
// 4) CSR fill: slot edges under their dst (int atomics; order immaterial)
// ---------------------------------------------------------------------------
__global__ void csr_fill_kernel(const int* __restrict__ src,
                                const int* __restrict__ dst, int n_edges) {
    int stride = gridDim.x * blockDim.x;
    for (int e = blockIdx.x * blockDim.x + threadIdx.x; e < n_edges; e += stride) {
        int d = __ldg(dst + e);
        int pos = atomicAdd(&g_cursor[d], 1);
        g_csr[pos] = __ldg(src + e);
    }
}

// ---------------------------------------------------------------------------
// 5) fused gather + GEMM + bias + relu
//    A_row = [x_row | mean_{nb in csr(row)} x_nb]  (1x128)
//    out   = relu(A @ [W_self; W_neigh] + b)
// 256 threads, 128-row tile. Full A tile staged in (dynamic) shared.
// Shared: Wsh 128x64 (32KB) + Atile 128x132 (67.6KB) + bias = ~100.6KB
// -> 2 blocks/SM, 16 warps/SM; FMA-bound mainloop.
// ---------------------------------------------------------------------------
#define GEMM_SMEM_FLOATS (128 * 64 + 128 * 132 + 64)
#define GEMM_SMEM_BYTES (GEMM_SMEM_FLOATS * 4)

__global__ __launch_bounds__(256) void sage_fused_kernel(
    const float* __restrict__ x,
    const float* __restrict__ Wself,
    const float* __restrict__ Wneigh,
    const float* __restrict__ bias,
    float* __restrict__ out,
    int n_rows) {

    extern __shared__ float smem[];
    float (*Wsh)[64] = (float(*)[64])smem;                    // [k][c]
    float (*Atile)[132] = (float(*)[132])(smem + 128 * 64);   // [row][k]
    float* bsh = smem + 128 * 64 + 128 * 132;

    const int tid = threadIdx.x;
    const int row0 = blockIdx.x * TILE_ROWS;

    // Combined weights into shared (k<64 -> W_self, k>=64 -> W_neigh)
    for (int i = tid; i < 64 * 64; i += 256) {
        int k = i >> 6, c = i & 63;
        Wsh[k][c] = __ldg(Wself + i);
    }
    for (int i = tid; i < 64 * 64; i += 256) {
        int k = i >> 6, c = i & 63;
        Wsh[k + 64][c] = __ldg(Wneigh + i);
    }
    if (tid < 64) bsh[tid] = __ldg(bias + tid);

    // x half of A: 128 rows x 16 float4
    for (int idx = tid; idx < 128 * 16; idx += 256) {
        int r = idx >> 4, c = idx & 15;
        int grow = row0 + r;
        float4 v = make_float4(0.f, 0.f, 0.f, 0.f);
        if (grow < n_rows)
            v = __ldg(reinterpret_cast<const float4*>(x + (size_t)grow * FEATS) + c);
        *reinterpret_cast<float4*>(&Atile[r][c * 4]) = v;
    }

    // neigh half: pull-aggregate via CSR. 16 threads/row, 16 rows per pass.
    // Degree loop unrolled x2 for MLP>=2 against L2 hit latency (~250cyc).
    {
        const int rsub = tid >> 4;   // 0..15
        const int c = tid & 15;      // float4 lane within the 64-f row
        for (int g = 0; g < 8; g++) {
            const int r = g * 16 + rsub;
            const int grow = row0 + r;
            float4 acc = make_float4(0.f, 0.f, 0.f, 0.f);
            if (grow < n_rows) {
                const int beg = __ldg(&g_off[grow]);
                const int deg = __ldg(&g_count[grow]);
                int j = 0;
                for (; j + 1 < deg; j += 2) {
                    const int nb0 = __ldg(&g_csr[beg + j]);
                    const int nb1 = __ldg(&g_csr[beg + j + 1]);
                    const float4 v0 = __ldg(reinterpret_cast<const float4*>(
                                                x + (size_t)nb0 * FEATS) + c);
                    const float4 v1 = __ldg(reinterpret_cast<const float4*>(
                                                x + (size_t)nb1 * FEATS) + c);
                    acc.x += v0.x + v1.x; acc.y += v0.y + v1.y;
                    acc.z += v0.z + v1.z; acc.w += v0.w + v1.w;
                }
                if (j < deg) {
                    const int nb = __ldg(&g_csr[beg + j]);
                    const float4 v = __ldg(reinterpret_cast<const float4*>(
                                               x + (size_t)nb * FEATS) + c);
                    acc.x += v.x; acc.y += v.y; acc.z += v.z; acc.w += v.w;
                }
                const float inv = 1.0f / fmaxf((float)deg, 1.0f);
                acc.x *= inv; acc.y *= inv; acc.z *= inv; acc.w *= inv;
            }
            *reinterpret_cast<float4*>(&Atile[r][64 + c * 4]) = acc;
        }
    }
    __syncthreads();

    // GEMM mainloop: thread tile 8 rows x 4 cols
    const int cg = tid & 15;   // cols cg*4..+3
    const int rg = tid >> 4;   // rows rg*8..+7

    float acc[8][4];
#pragma unroll
    for (int i = 0; i < 8; i++)
#pragma unroll
        for (int j = 0; j < 4; j++) acc[i][j] = 0.f;

    for (int kb = 0; kb < 128; kb += 16) {   // keep unrolled body I$-sized
#pragma unroll
        for (int kk = 0; kk < 16; kk++) {
            const int k = kb + kk;
            const float4 b4 = *reinterpret_cast<const float4*>(&Wsh[k][cg * 4]);
#pragma unroll
            for (int i = 0; i < 8; i++) {
                const float a = Atile[rg * 8 + i][k];
                acc[i][0] = fmaf(a, b4.x, acc[i][0]);
                acc[i][1] = fmaf(a, b4.y, acc[i][1]);
                acc[i][2] = fmaf(a, b4.z, acc[i][2]);
                acc[i][3] = fmaf(a, b4.w, acc[i][3]);
            }
        }
    }

    // Epilogue: bias + relu, vectorized store
    const float4 bb = *reinterpret_cast<const float4*>(&bsh[cg * 4]);
#pragma unroll
    for (int i = 0; i < 8; i++) {
        const int r = row0 + rg * 8 + i;
        if (r < n_rows) {
            float4 o;
            o.x = fmaxf(acc[i][0] + bb.x, 0.f);
            o.y = fmaxf(acc[i][1] + bb.y, 0.f);
            o.z = fmaxf(acc[i][2] + bb.z, 0.f);
            o.w = fmaxf(acc[i][3] + bb.w, 0.f);
            *reinterpret_cast<float4*>(out + (size_t)r * FEATS + cg * 4) = o;
        }
    }
}

// ---------------------------------------------------------------------------
// Launch. Inputs (metadata order): x, W_self, W_neigh, b, src, dst, num_dst
// ---------------------------------------------------------------------------
extern "C" void kernel_launch(void* const* d_in, const int* in_sizes, int n_in,
                              void* d_out, int out_size) {
    const float* x      = (const float*)d_in[0];
    const float* Wself  = (const float*)d_in[1];
    const float* Wneigh = (const float*)d_in[2];
    const float* bias   = (const float*)d_in[3];
    const int*   src    = (const int*)d_in[4];
    const int*   dst    = (const int*)d_in[5];

    const int n_src   = in_sizes[0] / FEATS;
    const int n_edges = in_sizes[4];
    const int num_dst = n_src;
    float* out = (float*)d_out;

    // CSR build (int-only; no float atomics anywhere)
    zero_counts_kernel<<<256, 256>>>(num_dst);
    hist_kernel<<<1024, 256>>>(dst, n_edges);

    const int C = (num_dst + SCAN_B - 1) / SCAN_B;     // elems per scan block
    const int S = (C + SCAN_T - 1) / SCAN_T;           // elems per scan thread
    scan_reduce_kernel<<<SCAN_B, SCAN_T>>>(num_dst, C);
    scan_partials_kernel<<<1, 32>>>();
    scan_final_kernel<<<SCAN_B, SCAN_T>>>(num_dst, C, S);

    csr_fill_kernel<<<1024, 256>>>(src, dst, n_edges);

    // Fused gather + GEMM
    cudaFuncSetAttribute(sage_fused_kernel,
                         cudaFuncAttributeMaxDynamicSharedMemorySize,
                         GEMM_SMEM_BYTES);
    const int blocks = (num_dst + TILE_ROWS - 1) / TILE_ROWS;
    sage_fused_kernel<<<blocks, 256, GEMM_SMEM_BYTES>>>(x, Wself, Wneigh, bias,
                                                        out, num_dst);
}